// round 13
// baseline (speedup 1.0000x reference)
#include <cuda_runtime.h>
#include <cuda_bf16.h>

// Embedding gather: out[t, :] = W_E[tokens[t], :]
// tokens: int32 [32768]   (d_in[0])
// W_E:    float32 [50257, 768]  (d_in[1])
// out:    float32 [32768, 768]
//
// R12 -> R13: .cs (evict-first) stores are the proven steady-state lever: the
// two .cs variants (R8, R12) hold the best dur_us (31.2) because ncu kernel
// time is cold-cache while dur_us measures warm graph replays, where .cs keeps
// W_E resident in L2 across replays. This round keeps plain __ldg reads +
// st.global.cs writes and software-pipelines two 8-token groups per CTA:
// group B's token-index loads overlap group A's row-load latency, and group
// B's row loads issue before group A's stores, halving CTA count (2048 CTAs).

#define D_MODEL 768
#define V4 (D_MODEL / 4)   // 192 float4 per row
#define U 8                // tokens per group
#define TOKENS_PER_CTA (2 * U)

__device__ __forceinline__ void store_cs(float4* dst, const float4& v) {
    asm volatile(
        "st.global.cs.v4.f32 [%0], {%1, %2, %3, %4};"
        :: "l"(dst), "f"(v.x), "f"(v.y), "f"(v.z), "f"(v.w)
        : "memory");
}

__global__ __launch_bounds__(V4) void embed_gather_kernel(
    const int* __restrict__ tokens,
    const float4* __restrict__ W,
    float4* __restrict__ out,
    int n_tok)
{
    const int col = threadIdx.x;
    const int t0  = blockIdx.x * TOKENS_PER_CTA;

    if (t0 + TOKENS_PER_CTA <= n_tok) {
        // Group A indices + row loads.
        int rowsA[U];
#pragma unroll
        for (int u = 0; u < U; ++u)
            rowsA[u] = __ldg(tokens + t0 + u);

        float4 vA[U];
#pragma unroll
        for (int u = 0; u < U; ++u)
            vA[u] = __ldg(W + (size_t)rowsA[u] * V4 + col);

        // Group B indices issue while group A row loads are in flight.
        int rowsB[U];
#pragma unroll
        for (int u = 0; u < U; ++u)
            rowsB[u] = __ldg(tokens + t0 + U + u);

        // Group B row loads issue before group A stores drain.
        float4 vB[U];
#pragma unroll
        for (int u = 0; u < U; ++u)
            vB[u] = __ldg(W + (size_t)rowsB[u] * V4 + col);

#pragma unroll
        for (int u = 0; u < U; ++u)
            store_cs(out + (size_t)(t0 + u) * V4 + col, vA[u]);

#pragma unroll
        for (int u = 0; u < U; ++u)
            store_cs(out + (size_t)(t0 + U + u) * V4 + col, vB[u]);
    } else {
        for (int t = t0; t < n_tok; ++t) {
            int row = __ldg(tokens + t);
            float4 v = __ldg(W + (size_t)row * V4 + col);
            store_cs(out + (size_t)t * V4 + col, v);
        }
    }
}

extern "C" void kernel_launch(void* const* d_in, const int* in_sizes, int n_in,
                              void* d_out, int out_size)
{
    const int* tokens = (const int*)d_in[0];
    const float4* W   = (const float4*)d_in[1];
    float4* out       = (float4*)d_out;

    const int n_tok = in_sizes[0];   // 32768
    const int grid  = (n_tok + TOKENS_PER_CTA - 1) / TOKENS_PER_CTA;  // 2048

    embed_gather_kernel<<<grid, V4>>>(tokens, W, out, n_tok);
}

// round 14
// speedup vs baseline: 1.0058x; 1.0058x over previous
#include <cuda_runtime.h>
#include <cuda_bf16.h>

// Embedding gather: out[t, :] = W_E[tokens[t], :]
// tokens: int32 [32768]   (d_in[0])
// W_E:    float32 [50257, 768]  (d_in[1])
// out:    float32 [32768, 768]
//
// FINAL (R14 = R12 record config). Session summary: register-MLP, cp.async.bulk
// (one-shot + persistent pipelined), cp.async 4-stage ring, L2 policy hints,
// and 256-bit LDG/STG all converge at a ~4.7-4.9 TB/s mixed random-read +
// streaming-write DRAM ceiling (~123-127 MB/launch). Best measured combo:
//   - 8 tokens per 192-thread CTA, batched __ldg float4 loads (MLP=8, 32 regs,
//     occ ~75%)
//   - st.global.cs (evict-first) stores: keeps W_E's ~74MB working set
//     L2-resident across warm graph replays (dur_us is warm; ncu is cold)
// R13's 16-token pipeline attempt regressed (ptxas re-serialized at 32 regs).

#define D_MODEL 768
#define V4 (D_MODEL / 4)   // 192 float4 per row
#define U 8                // tokens per CTA

__global__ __launch_bounds__(V4) void embed_gather_kernel(
    const int* __restrict__ tokens,
    const float4* __restrict__ W,
    float4* __restrict__ out,
    int n_tok)
{
    const int col = threadIdx.x;
    const int t0  = blockIdx.x * U;

    if (t0 + U <= n_tok) {
        int rows[U];
#pragma unroll
        for (int u = 0; u < U; ++u)
            rows[u] = __ldg(tokens + t0 + u);       // independent, L2-hot

        float4 v[U];
#pragma unroll
        for (int u = 0; u < U; ++u)
            v[u] = __ldg(W + (size_t)rows[u] * V4 + col);   // 8 independent 128B/warp loads

#pragma unroll
        for (int u = 0; u < U; ++u) {
            float4* dst = out + (size_t)(t0 + u) * V4 + col;
            asm volatile(
                "st.global.cs.v4.f32 [%0], {%1, %2, %3, %4};"
                :: "l"(dst), "f"(v[u].x), "f"(v[u].y), "f"(v[u].z), "f"(v[u].w)
                : "memory");
        }
    } else {
        for (int t = t0; t < n_tok; ++t) {
            int row = __ldg(tokens + t);
            float4 v = __ldg(W + (size_t)row * V4 + col);
            float4* dst = out + (size_t)t * V4 + col;
            asm volatile(
                "st.global.cs.v4.f32 [%0], {%1, %2, %3, %4};"
                :: "l"(dst), "f"(v.x), "f"(v.y), "f"(v.z), "f"(v.w)
                : "memory");
        }
    }
}

extern "C" void kernel_launch(void* const* d_in, const int* in_sizes, int n_in,
                              void* d_out, int out_size)
{
    const int* tokens = (const int*)d_in[0];
    const float4* W   = (const float4*)d_in[1];
    float4* out       = (float4*)d_out;

    const int n_tok = in_sizes[0];   // 32768
    const int grid  = (n_tok + U - 1) / U;

    embed_gather_kernel<<<grid, V4>>>(tokens, W, out, n_tok);
}